// round 12
// baseline (speedup 1.0000x reference)
#include <cuda_runtime.h>
#include <math.h>

typedef unsigned long long ull;

#define NT    70
#define NSEG  69
#define NS    11
#define OBS   8
#define BLK   128
#define MAXSLOT 16

__constant__ float c_times[16] = {0.f,2.f,4.f,6.f,8.f,10.f,12.f,14.f,
                                  16.f,18.f,20.f,25.f,30.f,40.f,50.f,60.f};
__constant__ float c_epo[16]   = {0.01713f,0.145f,0.2442f,0.7659f,1.0f,0.8605f,
                                  0.7829f,0.5705f,0.6217f,0.331f,0.3388f,0.3116f,
                                  0.05062f,0.02504f,0.01163f,0.01163f};

// ---- packed f32x2 helpers ----
__device__ __forceinline__ ull pk2(float lo, float hi) {
    ull r; asm("mov.b64 %0, {%1, %2};" : "=l"(r) : "f"(lo), "f"(hi)); return r;
}
__device__ __forceinline__ void upk2(ull v, float& lo, float& hi) {
    asm("mov.b64 {%0, %1}, %2;" : "=f"(lo), "=f"(hi) : "l"(v));
}
__device__ __forceinline__ ull f2fma(ull a, ull b, ull c) {
    ull r; asm("fma.rn.f32x2 %0, %1, %2, %3;" : "=l"(r) : "l"(a), "l"(b), "l"(c)); return r;
}
__device__ __forceinline__ ull f2mul(ull a, ull b) {
    ull r; asm("mul.rn.f32x2 %0, %1, %2;" : "=l"(r) : "l"(a), "l"(b)); return r;
}
__device__ __forceinline__ ull f2add(ull a, ull b) {
    ull r; asm("add.rn.f32x2 %0, %1, %2;" : "=l"(r) : "l"(a), "l"(b)); return r;
}
__device__ __forceinline__ ull f2sub(ull a, ull b) {
    ull r; asm("sub.rn.f32x2 %0, %1, %2;" : "=l"(r) : "l"(a), "l"(b)); return r;
}

__device__ __forceinline__ float epo_interp(float t) {
    if (t <= c_times[0]) return c_epo[0];
    #pragma unroll
    for (int k = 1; k < 16; ++k) {
        if (t <= c_times[k]) {
            float w = (t - c_times[k-1]) / (c_times[k] - c_times[k-1]);
            return c_epo[k-1] + w * (c_epo[k] - c_epo[k-1]);
        }
    }
    return c_epo[15];
}

// RK4 one-step propagator coefficients for the linear delay chain dq/dt = r(prev - q).
__device__ __forceinline__ void chain_coefs(float z, float* c) {
    float z2 = z * z, z3 = z2 * z, z4 = z2 * z2;
    c[0]  = 1.0f - z + 0.5f*z2 - (1.0f/6.0f)*z3 + (1.0f/24.0f)*z4;  // m0
    c[1]  = z - z2 + 0.5f*z3 - (1.0f/6.0f)*z4;                      // m1
    c[2]  = 0.5f*z2 - 0.5f*z3 + 0.25f*z4;                           // m2
    c[3]  = (1.0f/6.0f)*z3 - (1.0f/6.0f)*z4;                        // m3
    c[4]  = (1.0f/24.0f)*z4;                                        // m4 (== v14)
    c[5]  = (1.0f/6.0f)*(z - z2 + 0.5f*z3 - 0.25f*z4);              // v11
    c[6]  = (1.0f/6.0f)*(z2 - z3 + 0.75f*z4);                       // v12
    c[7]  = (1.0f/6.0f)*(0.5f*z3 - 0.75f*z4);                       // v13
    c[8]  = (1.0f/6.0f)*(2.0f*z - z2 + 0.5f*z3);                    // v21
    c[9]  = (1.0f/6.0f)*(z2 - z3);                                  // v22
    c[10] = (1.0f/6.0f)*(2.0f*z - z2);                              // v31
    c[11] = z / 6.0f;                                               // v41
    c[12] = z2 / 6.0f;                                              // v32
    c[13] = z3 / 12.0f;                                             // v23
}

struct __align__(32) EPack { ull a, m, c, pad; };

__global__ __launch_bounds__(BLK, 2) void stats5_kernel(
    const float* __restrict__ params,   // (B,3)
    const float* __restrict__ design,   // (8,)
    const float* __restrict__ noise,    // (B,16)
    float* __restrict__ out,            // true (B,16) then noised (B,16)
    int B)
{
    __shared__ EPack sE[NSEG];
    __shared__ int   sSlot[NT];          // used only by epilogue + t=0
    __shared__ ull   sMaskLo, sMaskHi;   // event bitmask over time indices
    __shared__ int   sTLast;
    __shared__ int   sIdxS[OBS];
    __shared__ float sWS[OBS];
    __shared__ ull   sY1[MAXSLOT][BLK];
    __shared__ ull   sY2[MAXSLOT][BLK];

    const float dt  = 60.0f / 69.0f;
    const int tid = threadIdx.x;

    if (tid < NSEG) {
        float t0 = (float)tid * dt;
        float a = epo_interp(t0);
        float m = epo_interp(t0 + 0.5f * dt);
        float c = epo_interp(t0 + dt);
        sE[tid].a = pk2(a, a);
        sE[tid].m = pk2(m, m);
        sE[tid].c = pk2(c, c);
    }
    if (tid < OBS) {
        float d = design[tid];
        float u = d * (69.0f / 60.0f);
        int i = (int)floorf(u);
        if (i < 0) i = 0;
        if (i > NSEG - 1) i = NSEG - 1;
        sIdxS[tid] = i;
        sWS[tid]   = u - (float)i;
    }
    __syncthreads();
    if (tid == 0) {
        int needed[NT];
        #pragma unroll 1
        for (int t = 0; t < NT; ++t) needed[t] = 0;
        int tlast = 1;
        for (int j = 0; j < OBS; ++j) {
            needed[sIdxS[j]]     = 1;
            needed[sIdxS[j] + 1] = 1;
            if (sIdxS[j] + 1 > tlast) tlast = sIdxS[j] + 1;
        }
        int slot = 0;
        ull mlo = 0ULL, mhi = 0ULL;
        #pragma unroll 1
        for (int t = 0; t < NT; ++t) {
            if (needed[t]) {
                sSlot[t] = slot++;
                if (t < 64) mlo |= (1ULL << t);
                else        mhi |= (1ULL << (t - 64));
            } else {
                sSlot[t] = -1;
            }
        }
        sMaskLo = mlo;
        sMaskHi = mhi;
        sTLast  = tlast;
    }
    __syncthreads();

    int p = blockIdx.x * BLK + tid;      // pair index
    int nPairs = B >> 1;
    if (p >= nPairs) return;
    int b0 = 2 * p, b1 = 2 * p + 1;

    // Coalesced param loads: 6 floats = 3x float2 (8B-aligned: 24B stride)
    const float2* pp = (const float2*)(params + (size_t)6 * p);
    float2 q0 = pp[0], q1 = pp[1], q2 = pp[2];

    float k1a  = fmaf(normcdff(q0.x), 2.5f,  0.5f);
    float k2a  = fmaf(normcdff(q0.y), 0.15f, 0.05f);
    float ra   = 8.0f / fmaf(normcdff(q1.x), 6.0f, 4.0f);
    float k1b  = fmaf(normcdff(q1.y), 2.5f,  0.5f);
    float k2b  = fmaf(normcdff(q2.x), 0.15f, 0.05f);
    float rb   = 8.0f / fmaf(normcdff(q2.y), 6.0f, 4.0f);

    const float hdt = 0.5f * dt, dt6 = dt / 6.0f, dt3 = dt / 3.0f;

    const ull K1P  = pk2(k1a, k1b);
    const ull K2P  = pk2(k2a, k2b);
    const ull NK2  = pk2(-k2a, -k2b);
    const ull Hdt  = pk2(hdt, hdt);
    const ull Dt   = pk2(dt, dt);
    const ull G    = pk2(dt6, dt6);
    const ull G2   = pk2(dt3, dt3);
    const ull C33  = pk2(0.33f, 0.33f);
    const ull C26  = pk2(0.26f, 0.26f);

    // k2-folded out-stage functionals (lambda = h*r/2)
    float la = hdt * ra, lb = hdt * rb;
    float la2 = la*la, la3 = la2*la, lb2 = lb*lb, lb3 = lb2*lb;
    const ull P20 = pk2(k2a*(1.0f - la),               k2b*(1.0f - lb));
    const ull P21 = pk2(k2a*la,                        k2b*lb);
    const ull P30 = pk2(k2a*(1.0f - la + la2),         k2b*(1.0f - lb + lb2));
    const ull P31 = pk2(k2a*(la - 2.0f*la2),           k2b*(lb - 2.0f*lb2));
    const ull P32 = pk2(k2a*la2,                       k2b*lb2);
    const ull P40 = pk2(k2a*(1.0f - 2.0f*la + 2.0f*la2 - 2.0f*la3),
                        k2b*(1.0f - 2.0f*lb + 2.0f*lb2 - 2.0f*lb3));
    const ull P41 = pk2(k2a*2.0f*la*(1.0f - 2.0f*la + 3.0f*la2),
                        k2b*2.0f*lb*(1.0f - 2.0f*lb + 3.0f*lb2));
    const ull P42 = pk2(k2a*2.0f*la2*(1.0f - 3.0f*la), k2b*2.0f*lb2*(1.0f - 3.0f*lb));
    const ull P43 = pk2(k2a*2.0f*la3,                  k2b*2.0f*lb3);

    // Chain RK4 propagator coefficients
    float ca[14], cb[14];
    chain_coefs(dt * ra, ca);
    chain_coefs(dt * rb, cb);
    const ull M0  = pk2(ca[0],  cb[0]);
    const ull M1  = pk2(ca[1],  cb[1]);
    const ull M2  = pk2(ca[2],  cb[2]);
    const ull M3  = pk2(ca[3],  cb[3]);
    const ull M4  = pk2(ca[4],  cb[4]);
    const ull V11 = pk2(ca[5],  cb[5]);
    const ull V12 = pk2(ca[6],  cb[6]);
    const ull V13 = pk2(ca[7],  cb[7]);
    const ull V21 = pk2(ca[8],  cb[8]);
    const ull V22 = pk2(ca[9],  cb[9]);
    const ull V31 = pk2(ca[10], cb[10]);
    const ull V41 = pk2(ca[11], cb[11]);
    const ull V32 = pk2(ca[12], cb[12]);
    const ull V23 = pk2(ca[13], cb[13]);

    // State: x[0..2] = x1,x2,x3; x[3..10] = q1..q7,out
    ull x[NS];
    #pragma unroll
    for (int i = 0; i < NS; ++i) x[i] = 0ULL;
    x[0] = pk2(3.71f, 3.71f);

    int slotCtr = 0;
    if (sSlot[0] >= 0) {                  // t = 0 snapshot (y1=0, y2=0.26*3.71)
        const float y2s = 0.26f * 3.71f;
        sY1[0][tid] = 0ULL;
        sY2[0][tid] = pk2(y2s, y2s);
        slotCtr = 1;
    }

    const int tLast = sTLast;             // block-uniform loop bound
    // Rolling event mask positioned at bit (t+1): pre-shift right by 1
    ull mLo = sMaskLo, mHi = sMaskHi;
    mLo = (mLo >> 1) | (mHi << 63); mHi >>= 1;

    #pragma unroll 3
    for (int t = 0; t < tLast; ++t) {
        ulonglong2 eam = *reinterpret_cast<const ulonglong2*>(&sE[t].a);
        ull Ea = eam.x, Em = eam.y, Ec = sE[t].c;

        // ---- k2-scaled out-stage values (linear functionals of old chain) ----
        ull k2o1 = f2mul(K2P, x[10]);
        ull k2o2 = f2fma(P21, x[9], f2mul(P20, x[10]));
        ull k2o3 = f2fma(P32, x[8], f2fma(P31, x[9], f2mul(P30, x[10])));
        ull k2o4 = f2fma(P43, x[7], f2fma(P42, x[8],
                   f2fma(P41, x[9], f2mul(P40, x[10]))));

        // ---- Nonlinear block (x1,x2,x3), classic 4-stage RK4 ----
        ull kE, t1, xsq, s0, s1, s2;
        ull xn0, xn1, xn2, xt0, xt1, xt2;

        // stage 1
        kE  = f2mul(K1P, Ea);
        t1  = f2mul(kE, x[0]);
        xsq = f2mul(x[1], x[1]);
        s2 = f2fma(NK2, x[2], xsq);
        s1 = f2sub(t1, xsq);
        s0 = f2sub(k2o1, t1);
        xn0 = f2fma(G, s0, x[0]); xt0 = f2fma(Hdt, s0, x[0]);
        xn1 = f2fma(G, s1, x[1]); xt1 = f2fma(Hdt, s1, x[1]);
        xn2 = f2fma(G, s2, x[2]); xt2 = f2fma(Hdt, s2, x[2]);
        ull u1 = x[2];
        ull u2 = xt2;

        // stage 2 (E mid)
        ull kEm = f2mul(K1P, Em);
        t1  = f2mul(kEm, xt0);
        xsq = f2mul(xt1, xt1);
        s2 = f2fma(NK2, xt2, xsq);
        s1 = f2sub(t1, xsq);
        s0 = f2sub(k2o2, t1);
        xn0 = f2fma(G2, s0, xn0); xt0 = f2fma(Hdt, s0, x[0]);
        xn1 = f2fma(G2, s1, xn1); xt1 = f2fma(Hdt, s1, x[1]);
        xn2 = f2fma(G2, s2, xn2); xt2 = f2fma(Hdt, s2, x[2]);
        ull u3 = xt2;

        // stage 3 (E mid)
        t1  = f2mul(kEm, xt0);
        xsq = f2mul(xt1, xt1);
        s2 = f2fma(NK2, xt2, xsq);
        s1 = f2sub(t1, xsq);
        s0 = f2sub(k2o3, t1);
        xn0 = f2fma(G2, s0, xn0); xt0 = f2fma(Dt, s0, x[0]);
        xn1 = f2fma(G2, s1, xn1); xt1 = f2fma(Dt, s1, x[1]);
        xn2 = f2fma(G2, s2, xn2); xt2 = f2fma(Dt, s2, x[2]);
        ull u4 = xt2;

        // stage 4 (E hi)
        ull kEc = f2mul(K1P, Ec);
        t1  = f2mul(kEc, xt0);
        xsq = f2mul(xt1, xt1);
        s2 = f2fma(NK2, xt2, xsq);
        s1 = f2sub(t1, xsq);
        s0 = f2sub(k2o4, t1);
        x[0] = f2fma(G, s0, xn0);
        x[1] = f2fma(G, s1, xn1);
        x[2] = f2fma(G, s2, xn2);

        // ---- Chain update: q' = M q + v-weighted stage inputs ----
        ull a;
        a = f2mul(M0, x[10]); a = f2fma(M1, x[9], a); a = f2fma(M2, x[8], a);
        a = f2fma(M3, x[7], a); x[10] = f2fma(M4, x[6], a);
        a = f2mul(M0, x[9]);  a = f2fma(M1, x[8], a); a = f2fma(M2, x[7], a);
        a = f2fma(M3, x[6], a); x[9] = f2fma(M4, x[5], a);
        a = f2mul(M0, x[8]);  a = f2fma(M1, x[7], a); a = f2fma(M2, x[6], a);
        a = f2fma(M3, x[5], a); x[8] = f2fma(M4, x[4], a);
        a = f2mul(M0, x[7]);  a = f2fma(M1, x[6], a); a = f2fma(M2, x[5], a);
        a = f2fma(M3, x[4], a); x[7] = f2fma(M4, x[3], a);
        a = f2mul(M0, x[6]);  a = f2fma(M1, x[5], a); a = f2fma(M2, x[4], a);
        a = f2fma(M3, x[3], a); x[6] = f2fma(M4, u1, a);
        a = f2mul(M0, x[5]);  a = f2fma(M1, x[4], a); a = f2fma(M2, x[3], a);
        a = f2fma(V13, u1, a); x[5] = f2fma(V23, u2, a);
        a = f2mul(M0, x[4]);  a = f2fma(M1, x[3], a); a = f2fma(V12, u1, a);
        a = f2fma(V22, u2, a); x[4] = f2fma(V32, u3, a);
        a = f2mul(M0, x[3]);  a = f2fma(V11, u1, a); a = f2fma(V21, u2, a);
        a = f2fma(V31, u3, a); x[3] = f2fma(V41, u4, a);

        // ---- Snapshot at flagged steps: rolling bitmask + slot counter ----
        if (mLo & 1ULL) {
            ull y1 = f2mul(C33, f2add(x[1], x[2]));
            ull y2 = f2mul(C26, f2add(f2add(x[0], x[1]), x[2]));
            sY1[slotCtr][tid] = y1;
            sY2[slotCtr][tid] = y2;
            ++slotCtr;
        }
        mLo = (mLo >> 1) | (mHi << 63); mHi >>= 1;
    }

    // ===== Epilogue: design-point interpolation from shared snapshots
    float r0[16], r1[16];
    #pragma unroll
    for (int j = 0; j < OBS; ++j) {
        int   i  = sIdxS[j];
        float w  = sWS[j];
        int   sa = sSlot[i];
        int   sb = sSlot[i + 1];
        ull W  = pk2(w, w);
        ull WM = pk2(1.0f - w, 1.0f - w);

        ull o1v = f2fma(WM, sY1[sa][tid], f2mul(W, sY1[sb][tid]));
        ull o2v = f2fma(WM, sY2[sa][tid], f2mul(W, sY2[sb][tid]));

        float a1, bv1, a2, bv2;
        upk2(o1v, a1, bv1);
        upk2(o2v, a2, bv2);
        r0[j] = a1;  r0[j + 8] = a2;
        r1[j] = bv1; r1[j + 8] = bv2;
    }

    float4*       tr0 = (float4*)(out + (size_t)b0 * 16);
    float4*       tr1 = (float4*)(out + (size_t)b1 * 16);
    float4*       nz0 = (float4*)(out + (size_t)B * 16 + (size_t)b0 * 16);
    float4*       nz1 = (float4*)(out + (size_t)B * 16 + (size_t)b1 * 16);
    const float4* ns0 = (const float4*)(noise + (size_t)b0 * 16);
    const float4* ns1 = (const float4*)(noise + (size_t)b1 * 16);

    #pragma unroll
    for (int q = 0; q < 4; ++q) {
        float4 n0 = ns0[q], n1 = ns1[q];
        tr0[q] = make_float4(r0[4*q], r0[4*q+1], r0[4*q+2], r0[4*q+3]);
        tr1[q] = make_float4(r1[4*q], r1[4*q+1], r1[4*q+2], r1[4*q+3]);
        nz0[q] = make_float4(fmaf(0.01f, n0.x, r0[4*q]),   fmaf(0.01f, n0.y, r0[4*q+1]),
                             fmaf(0.01f, n0.z, r0[4*q+2]), fmaf(0.01f, n0.w, r0[4*q+3]));
        nz1[q] = make_float4(fmaf(0.01f, n1.x, r1[4*q]),   fmaf(0.01f, n1.y, r1[4*q+1]),
                             fmaf(0.01f, n1.z, r1[4*q+2]), fmaf(0.01f, n1.w, r1[4*q+3]));
    }
}

extern "C" void kernel_launch(void* const* d_in, const int* in_sizes, int n_in,
                              void* d_out, int out_size) {
    const float* params = (const float*)d_in[0];
    const float* design = (const float*)d_in[1];
    const float* noise  = (const float*)d_in[2];
    float* out = (float*)d_out;
    int B = in_sizes[0] / 3;

    int nPairs = B >> 1;
    int blocks = (nPairs + BLK - 1) / BLK;
    stats5_kernel<<<blocks, BLK>>>(params, design, noise, out, B);
}

// round 13
// speedup vs baseline: 1.0341x; 1.0341x over previous
#include <cuda_runtime.h>
#include <math.h>

typedef unsigned long long ull;

#define NT    70
#define NSEG  69
#define NS    11
#define OBS   8
#define BLK   128
#define MAXSLOT 16

__constant__ float c_times[16] = {0.f,2.f,4.f,6.f,8.f,10.f,12.f,14.f,
                                  16.f,18.f,20.f,25.f,30.f,40.f,50.f,60.f};
__constant__ float c_epo[16]   = {0.01713f,0.145f,0.2442f,0.7659f,1.0f,0.8605f,
                                  0.7829f,0.5705f,0.6217f,0.331f,0.3388f,0.3116f,
                                  0.05062f,0.02504f,0.01163f,0.01163f};

// ---- packed f32x2 helpers ----
__device__ __forceinline__ ull pk2(float lo, float hi) {
    ull r; asm("mov.b64 %0, {%1, %2};" : "=l"(r) : "f"(lo), "f"(hi)); return r;
}
__device__ __forceinline__ void upk2(ull v, float& lo, float& hi) {
    asm("mov.b64 {%0, %1}, %2;" : "=f"(lo), "=f"(hi) : "l"(v));
}
__device__ __forceinline__ ull f2fma(ull a, ull b, ull c) {
    ull r; asm("fma.rn.f32x2 %0, %1, %2, %3;" : "=l"(r) : "l"(a), "l"(b), "l"(c)); return r;
}
__device__ __forceinline__ ull f2mul(ull a, ull b) {
    ull r; asm("mul.rn.f32x2 %0, %1, %2;" : "=l"(r) : "l"(a), "l"(b)); return r;
}
__device__ __forceinline__ ull f2add(ull a, ull b) {
    ull r; asm("add.rn.f32x2 %0, %1, %2;" : "=l"(r) : "l"(a), "l"(b)); return r;
}
__device__ __forceinline__ ull f2sub(ull a, ull b) {
    ull r; asm("sub.rn.f32x2 %0, %1, %2;" : "=l"(r) : "l"(a), "l"(b)); return r;
}

__device__ __forceinline__ float epo_interp(float t) {
    if (t <= c_times[0]) return c_epo[0];
    #pragma unroll
    for (int k = 1; k < 16; ++k) {
        if (t <= c_times[k]) {
            float w = (t - c_times[k-1]) / (c_times[k] - c_times[k-1]);
            return c_epo[k-1] + w * (c_epo[k] - c_epo[k-1]);
        }
    }
    return c_epo[15];
}

// RK4 one-step propagator coefficients for the linear delay chain dq/dt = r(prev - q).
__device__ __forceinline__ void chain_coefs(float z, float* c) {
    float z2 = z * z, z3 = z2 * z, z4 = z2 * z2;
    c[0]  = 1.0f - z + 0.5f*z2 - (1.0f/6.0f)*z3 + (1.0f/24.0f)*z4;  // m0
    c[1]  = z - z2 + 0.5f*z3 - (1.0f/6.0f)*z4;                      // m1
    c[2]  = 0.5f*z2 - 0.5f*z3 + 0.25f*z4;                           // m2
    c[3]  = (1.0f/6.0f)*z3 - (1.0f/6.0f)*z4;                        // m3
    c[4]  = (1.0f/24.0f)*z4;                                        // m4 (== v14)
    c[5]  = (1.0f/6.0f)*(z - z2 + 0.5f*z3 - 0.25f*z4);              // v11
    c[6]  = (1.0f/6.0f)*(z2 - z3 + 0.75f*z4);                       // v12
    c[7]  = (1.0f/6.0f)*(0.5f*z3 - 0.75f*z4);                       // v13
    c[8]  = (1.0f/6.0f)*(2.0f*z - z2 + 0.5f*z3);                    // v21
    c[9]  = (1.0f/6.0f)*(z2 - z3);                                  // v22
    c[10] = (1.0f/6.0f)*(2.0f*z - z2);                              // v31
    c[11] = z / 6.0f;                                               // v41
    c[12] = z2 / 6.0f;                                              // v32
    c[13] = z3 / 12.0f;                                             // v23
}

struct __align__(32) EPack { ull a, m, c, pad; };

__global__ __launch_bounds__(BLK, 2) void stats5_kernel(
    const float* __restrict__ params,   // (B,3)
    const float* __restrict__ design,   // (8,)
    const float* __restrict__ noise,    // (B,16)
    float* __restrict__ out,            // true (B,16) then noised (B,16)
    int B)
{
    __shared__ EPack sE[NSEG];
    __shared__ int   sSlot[NT];
    __shared__ int   sTLast;             // last flagged time (loop bound)
    __shared__ int   sIdxS[OBS];
    __shared__ float sWS[OBS];
    __shared__ ull   sY1[MAXSLOT][BLK];
    __shared__ ull   sY2[MAXSLOT][BLK];

    const float dt  = 60.0f / 69.0f;
    const int tid = threadIdx.x;

    if (tid < NSEG) {
        float t0 = (float)tid * dt;
        float a = epo_interp(t0);
        float m = epo_interp(t0 + 0.5f * dt);
        float c = epo_interp(t0 + dt);
        sE[tid].a = pk2(a, a);
        sE[tid].m = pk2(m, m);
        sE[tid].c = pk2(c, c);
    }
    if (tid < OBS) {
        float d = design[tid];
        float u = d * (69.0f / 60.0f);
        int i = (int)floorf(u);
        if (i < 0) i = 0;
        if (i > NSEG - 1) i = NSEG - 1;
        sIdxS[tid] = i;
        sWS[tid]   = u - (float)i;
    }
    __syncthreads();
    if (tid == 0) {
        int needed[NT];
        #pragma unroll 1
        for (int t = 0; t < NT; ++t) needed[t] = 0;
        int tlast = 1;
        for (int j = 0; j < OBS; ++j) {
            needed[sIdxS[j]]     = 1;
            needed[sIdxS[j] + 1] = 1;
            if (sIdxS[j] + 1 > tlast) tlast = sIdxS[j] + 1;
        }
        int slot = 0;
        #pragma unroll 1
        for (int t = 0; t < NT; ++t)
            sSlot[t] = needed[t] ? slot++ : -1;
        sTLast = tlast;
    }
    __syncthreads();

    int p = blockIdx.x * BLK + tid;      // pair index
    int nPairs = B >> 1;
    if (p >= nPairs) return;
    int b0 = 2 * p, b1 = 2 * p + 1;

    // Coalesced param loads: 6 floats = 3x float2 (24B stride, 8B aligned)
    const float2* pp = (const float2*)(params + (size_t)6 * p);
    float2 q0 = pp[0], q1 = pp[1], q2 = pp[2];

    float k1a  = fmaf(normcdff(q0.x), 2.5f,  0.5f);
    float k2a  = fmaf(normcdff(q0.y), 0.15f, 0.05f);
    float ra   = 8.0f / fmaf(normcdff(q1.x), 6.0f, 4.0f);
    float k1b  = fmaf(normcdff(q1.y), 2.5f,  0.5f);
    float k2b  = fmaf(normcdff(q2.x), 0.15f, 0.05f);
    float rb   = 8.0f / fmaf(normcdff(q2.y), 6.0f, 4.0f);

    const float hdt = 0.5f * dt, dt6 = dt / 6.0f, dt3 = dt / 3.0f;

    const ull K1P  = pk2(k1a, k1b);
    const ull K2P  = pk2(k2a, k2b);
    const ull NK2  = pk2(-k2a, -k2b);
    const ull Hdt  = pk2(hdt, hdt);
    const ull Dt   = pk2(dt, dt);
    const ull G    = pk2(dt6, dt6);
    const ull G2   = pk2(dt3, dt3);
    const ull C33  = pk2(0.33f, 0.33f);
    const ull C26  = pk2(0.26f, 0.26f);

    // k2-folded out-stage functionals (lambda = h*r/2)
    float la = hdt * ra, lb = hdt * rb;
    float la2 = la*la, la3 = la2*la, lb2 = lb*lb, lb3 = lb2*lb;
    const ull P20 = pk2(k2a*(1.0f - la),               k2b*(1.0f - lb));
    const ull P21 = pk2(k2a*la,                        k2b*lb);
    const ull P30 = pk2(k2a*(1.0f - la + la2),         k2b*(1.0f - lb + lb2));
    const ull P31 = pk2(k2a*(la - 2.0f*la2),           k2b*(lb - 2.0f*lb2));
    const ull P32 = pk2(k2a*la2,                       k2b*lb2);
    const ull P40 = pk2(k2a*(1.0f - 2.0f*la + 2.0f*la2 - 2.0f*la3),
                        k2b*(1.0f - 2.0f*lb + 2.0f*lb2 - 2.0f*lb3));
    const ull P41 = pk2(k2a*2.0f*la*(1.0f - 2.0f*la + 3.0f*la2),
                        k2b*2.0f*lb*(1.0f - 2.0f*lb + 3.0f*lb2));
    const ull P42 = pk2(k2a*2.0f*la2*(1.0f - 3.0f*la), k2b*2.0f*lb2*(1.0f - 3.0f*lb));
    const ull P43 = pk2(k2a*2.0f*la3,                  k2b*2.0f*lb3);

    // Chain RK4 propagator coefficients
    float ca[14], cb[14];
    chain_coefs(dt * ra, ca);
    chain_coefs(dt * rb, cb);
    const ull M0  = pk2(ca[0],  cb[0]);
    const ull M1  = pk2(ca[1],  cb[1]);
    const ull M2  = pk2(ca[2],  cb[2]);
    const ull M3  = pk2(ca[3],  cb[3]);
    const ull M4  = pk2(ca[4],  cb[4]);
    const ull V11 = pk2(ca[5],  cb[5]);
    const ull V12 = pk2(ca[6],  cb[6]);
    const ull V13 = pk2(ca[7],  cb[7]);
    const ull V21 = pk2(ca[8],  cb[8]);
    const ull V22 = pk2(ca[9],  cb[9]);
    const ull V31 = pk2(ca[10], cb[10]);
    const ull V41 = pk2(ca[11], cb[11]);
    const ull V32 = pk2(ca[12], cb[12]);
    const ull V23 = pk2(ca[13], cb[13]);

    // State: x[0..2] = x1,x2,x3; x[3..10] = q1..q7,out
    ull x[NS];
    #pragma unroll
    for (int i = 0; i < NS; ++i) x[i] = 0ULL;
    x[0] = pk2(3.71f, 3.71f);

    {
        int sl = sSlot[0];
        if (sl >= 0) {
            const float y2s = 0.26f * 3.71f;
            sY1[sl][tid] = 0ULL;
            sY2[sl][tid] = pk2(y2s, y2s);
        }
    }

    const int tLast = sTLast;   // block-uniform; steps beyond are unobserved

    #pragma unroll 3
    for (int t = 0; t < tLast; ++t) {
        ulonglong2 eam = *reinterpret_cast<const ulonglong2*>(&sE[t].a);
        ull Ea = eam.x, Em = eam.y, Ec = sE[t].c;

        // ---- k2-scaled out-stage values (linear functionals of old chain) ----
        ull k2o1 = f2mul(K2P, x[10]);
        ull k2o2 = f2fma(P21, x[9], f2mul(P20, x[10]));
        ull k2o3 = f2fma(P32, x[8], f2fma(P31, x[9], f2mul(P30, x[10])));
        ull k2o4 = f2fma(P43, x[7], f2fma(P42, x[8],
                   f2fma(P41, x[9], f2mul(P40, x[10]))));

        // ---- Nonlinear block (x1,x2,x3), classic 4-stage RK4 ----
        ull kE, t1, xsq, s0, s1, s2;
        ull xn0, xn1, xn2, xt0, xt1, xt2;

        // stage 1
        kE  = f2mul(K1P, Ea);
        t1  = f2mul(kE, x[0]);
        xsq = f2mul(x[1], x[1]);
        s2 = f2fma(NK2, x[2], xsq);
        s1 = f2sub(t1, xsq);
        s0 = f2sub(k2o1, t1);
        xn0 = f2fma(G, s0, x[0]); xt0 = f2fma(Hdt, s0, x[0]);
        xn1 = f2fma(G, s1, x[1]); xt1 = f2fma(Hdt, s1, x[1]);
        xn2 = f2fma(G, s2, x[2]); xt2 = f2fma(Hdt, s2, x[2]);
        ull u1 = x[2];
        ull u2 = xt2;

        // stage 2 (E mid)
        ull kEm = f2mul(K1P, Em);
        t1  = f2mul(kEm, xt0);
        xsq = f2mul(xt1, xt1);
        s2 = f2fma(NK2, xt2, xsq);
        s1 = f2sub(t1, xsq);
        s0 = f2sub(k2o2, t1);
        xn0 = f2fma(G2, s0, xn0); xt0 = f2fma(Hdt, s0, x[0]);
        xn1 = f2fma(G2, s1, xn1); xt1 = f2fma(Hdt, s1, x[1]);
        xn2 = f2fma(G2, s2, xn2); xt2 = f2fma(Hdt, s2, x[2]);
        ull u3 = xt2;

        // stage 3 (E mid)
        t1  = f2mul(kEm, xt0);
        xsq = f2mul(xt1, xt1);
        s2 = f2fma(NK2, xt2, xsq);
        s1 = f2sub(t1, xsq);
        s0 = f2sub(k2o3, t1);
        xn0 = f2fma(G2, s0, xn0); xt0 = f2fma(Dt, s0, x[0]);
        xn1 = f2fma(G2, s1, xn1); xt1 = f2fma(Dt, s1, x[1]);
        xn2 = f2fma(G2, s2, xn2); xt2 = f2fma(Dt, s2, x[2]);
        ull u4 = xt2;

        // stage 4 (E hi)
        ull kEc = f2mul(K1P, Ec);
        t1  = f2mul(kEc, xt0);
        xsq = f2mul(xt1, xt1);
        s2 = f2fma(NK2, xt2, xsq);
        s1 = f2sub(t1, xsq);
        s0 = f2sub(k2o4, t1);
        x[0] = f2fma(G, s0, xn0);
        x[1] = f2fma(G, s1, xn1);
        x[2] = f2fma(G, s2, xn2);

        // ---- Chain update: q' = M q + v-weighted stage inputs ----
        ull a;
        a = f2mul(M0, x[10]); a = f2fma(M1, x[9], a); a = f2fma(M2, x[8], a);
        a = f2fma(M3, x[7], a); x[10] = f2fma(M4, x[6], a);
        a = f2mul(M0, x[9]);  a = f2fma(M1, x[8], a); a = f2fma(M2, x[7], a);
        a = f2fma(M3, x[6], a); x[9] = f2fma(M4, x[5], a);
        a = f2mul(M0, x[8]);  a = f2fma(M1, x[7], a); a = f2fma(M2, x[6], a);
        a = f2fma(M3, x[5], a); x[8] = f2fma(M4, x[4], a);
        a = f2mul(M0, x[7]);  a = f2fma(M1, x[6], a); a = f2fma(M2, x[5], a);
        a = f2fma(M3, x[4], a); x[7] = f2fma(M4, x[3], a);
        a = f2mul(M0, x[6]);  a = f2fma(M1, x[5], a); a = f2fma(M2, x[4], a);
        a = f2fma(M3, x[3], a); x[6] = f2fma(M4, u1, a);
        a = f2mul(M0, x[5]);  a = f2fma(M1, x[4], a); a = f2fma(M2, x[3], a);
        a = f2fma(V13, u1, a); x[5] = f2fma(V23, u2, a);
        a = f2mul(M0, x[4]);  a = f2fma(M1, x[3], a); a = f2fma(V12, u1, a);
        a = f2fma(V22, u2, a); x[4] = f2fma(V32, u3, a);
        a = f2mul(M0, x[3]);  a = f2fma(V11, u1, a); a = f2fma(V21, u2, a);
        a = f2fma(V31, u3, a); x[3] = f2fma(V41, u4, a);

        // ---- Snapshot observables at flagged steps (uniform branch) ----
        int sl = sSlot[t + 1];
        if (sl >= 0) {
            ull y1 = f2mul(C33, f2add(x[1], x[2]));
            ull y2 = f2mul(C26, f2add(f2add(x[0], x[1]), x[2]));
            sY1[sl][tid] = y1;
            sY2[sl][tid] = y2;
        }
    }

    // ===== Epilogue: design-point interpolation from shared snapshots
    float r0[16], r1[16];
    #pragma unroll
    for (int j = 0; j < OBS; ++j) {
        int   i  = sIdxS[j];
        float w  = sWS[j];
        int   sa = sSlot[i];
        int   sb = sSlot[i + 1];
        ull W  = pk2(w, w);
        ull WM = pk2(1.0f - w, 1.0f - w);

        ull o1v = f2fma(WM, sY1[sa][tid], f2mul(W, sY1[sb][tid]));
        ull o2v = f2fma(WM, sY2[sa][tid], f2mul(W, sY2[sb][tid]));

        float a1, bv1, a2, bv2;
        upk2(o1v, a1, bv1);
        upk2(o2v, a2, bv2);
        r0[j] = a1;  r0[j + 8] = a2;
        r1[j] = bv1; r1[j + 8] = bv2;
    }

    float4*       tr0 = (float4*)(out + (size_t)b0 * 16);
    float4*       tr1 = (float4*)(out + (size_t)b1 * 16);
    float4*       nz0 = (float4*)(out + (size_t)B * 16 + (size_t)b0 * 16);
    float4*       nz1 = (float4*)(out + (size_t)B * 16 + (size_t)b1 * 16);
    const float4* ns0 = (const float4*)(noise + (size_t)b0 * 16);
    const float4* ns1 = (const float4*)(noise + (size_t)b1 * 16);

    #pragma unroll
    for (int q = 0; q < 4; ++q) {
        float4 n0 = ns0[q], n1 = ns1[q];
        tr0[q] = make_float4(r0[4*q], r0[4*q+1], r0[4*q+2], r0[4*q+3]);
        tr1[q] = make_float4(r1[4*q], r1[4*q+1], r1[4*q+2], r1[4*q+3]);
        nz0[q] = make_float4(fmaf(0.01f, n0.x, r0[4*q]),   fmaf(0.01f, n0.y, r0[4*q+1]),
                             fmaf(0.01f, n0.z, r0[4*q+2]), fmaf(0.01f, n0.w, r0[4*q+3]));
        nz1[q] = make_float4(fmaf(0.01f, n1.x, r1[4*q]),   fmaf(0.01f, n1.y, r1[4*q+1]),
                             fmaf(0.01f, n1.z, r1[4*q+2]), fmaf(0.01f, n1.w, r1[4*q+3]));
    }
}

extern "C" void kernel_launch(void* const* d_in, const int* in_sizes, int n_in,
                              void* d_out, int out_size) {
    const float* params = (const float*)d_in[0];
    const float* design = (const float*)d_in[1];
    const float* noise  = (const float*)d_in[2];
    float* out = (float*)d_out;
    int B = in_sizes[0] / 3;

    int nPairs = B >> 1;
    int blocks = (nPairs + BLK - 1) / BLK;
    stats5_kernel<<<blocks, BLK>>>(params, design, noise, out, B);
}

// round 14
// speedup vs baseline: 1.0820x; 1.0463x over previous
#include <cuda_runtime.h>
#include <math.h>

typedef unsigned long long ull;

#define NT    70
#define NSEG  69
#define NS    11
#define OBS   8
#define BLK   128
#define MAXSLOT 16

// Broadcast a (compile-time) float into both halves of a packed f32x2 word.
// Constant-folds to a 64-bit immediate -> uniform -> UR-promotable by ptxas.
#define PKC(f) ((((ull)__float_as_uint(f)) << 32) | (ull)__float_as_uint(f))

__constant__ float c_times[16] = {0.f,2.f,4.f,6.f,8.f,10.f,12.f,14.f,
                                  16.f,18.f,20.f,25.f,30.f,40.f,50.f,60.f};
__constant__ float c_epo[16]   = {0.01713f,0.145f,0.2442f,0.7659f,1.0f,0.8605f,
                                  0.7829f,0.5705f,0.6217f,0.331f,0.3388f,0.3116f,
                                  0.05062f,0.02504f,0.01163f,0.01163f};

// ---- packed f32x2 helpers ----
__device__ __forceinline__ ull pk2(float lo, float hi) {
    ull r; asm("mov.b64 %0, {%1, %2};" : "=l"(r) : "f"(lo), "f"(hi)); return r;
}
__device__ __forceinline__ void upk2(ull v, float& lo, float& hi) {
    asm("mov.b64 {%0, %1}, %2;" : "=f"(lo), "=f"(hi) : "l"(v));
}
__device__ __forceinline__ ull f2fma(ull a, ull b, ull c) {
    ull r; asm("fma.rn.f32x2 %0, %1, %2, %3;" : "=l"(r) : "l"(a), "l"(b), "l"(c)); return r;
}
__device__ __forceinline__ ull f2mul(ull a, ull b) {
    ull r; asm("mul.rn.f32x2 %0, %1, %2;" : "=l"(r) : "l"(a), "l"(b)); return r;
}
__device__ __forceinline__ ull f2add(ull a, ull b) {
    ull r; asm("add.rn.f32x2 %0, %1, %2;" : "=l"(r) : "l"(a), "l"(b)); return r;
}
__device__ __forceinline__ ull f2sub(ull a, ull b) {
    ull r; asm("sub.rn.f32x2 %0, %1, %2;" : "=l"(r) : "l"(a), "l"(b)); return r;
}

__device__ __forceinline__ float epo_interp(float t) {
    if (t <= c_times[0]) return c_epo[0];
    #pragma unroll
    for (int k = 1; k < 16; ++k) {
        if (t <= c_times[k]) {
            float w = (t - c_times[k-1]) / (c_times[k] - c_times[k-1]);
            return c_epo[k-1] + w * (c_epo[k] - c_epo[k-1]);
        }
    }
    return c_epo[15];
}

// RK4 one-step propagator coefficients for the linear delay chain dq/dt = r(prev - q).
__device__ __forceinline__ void chain_coefs(float z, float* c) {
    float z2 = z * z, z3 = z2 * z, z4 = z2 * z2;
    c[0]  = 1.0f - z + 0.5f*z2 - (1.0f/6.0f)*z3 + (1.0f/24.0f)*z4;  // m0
    c[1]  = z - z2 + 0.5f*z3 - (1.0f/6.0f)*z4;                      // m1
    c[2]  = 0.5f*z2 - 0.5f*z3 + 0.25f*z4;                           // m2
    c[3]  = (1.0f/6.0f)*z3 - (1.0f/6.0f)*z4;                        // m3
    c[4]  = (1.0f/24.0f)*z4;                                        // m4 (== v14)
    c[5]  = (1.0f/6.0f)*(z - z2 + 0.5f*z3 - 0.25f*z4);              // v11
    c[6]  = (1.0f/6.0f)*(z2 - z3 + 0.75f*z4);                       // v12
    c[7]  = (1.0f/6.0f)*(0.5f*z3 - 0.75f*z4);                       // v13
    c[8]  = (1.0f/6.0f)*(2.0f*z - z2 + 0.5f*z3);                    // v21
    c[9]  = (1.0f/6.0f)*(z2 - z3);                                  // v22
    c[10] = (1.0f/6.0f)*(2.0f*z - z2);                              // v31
    c[11] = z / 6.0f;                                               // v41
    c[12] = z2 / 6.0f;                                              // v32
    c[13] = z3 / 12.0f;                                             // v23
}

__global__ __launch_bounds__(BLK, 2) void stats5_kernel(
    const float* __restrict__ params,   // (B,3)
    const float* __restrict__ design,   // (8,)
    const float* __restrict__ noise,    // (B,16)
    float* __restrict__ out,            // true (B,16) then noised (B,16)
    int B)
{
    __shared__ ulonglong2 sE2[NT];       // [t] = (Ea(t), Em(t)); Ec(t) = Ea(t+1)
    __shared__ int   sSlot[NT];
    __shared__ int   sTLast;
    __shared__ int   sIdxS[OBS];
    __shared__ float sWS[OBS];
    __shared__ ull   sY1[MAXSLOT][BLK];
    __shared__ ull   sY2[MAXSLOT][BLK];

    const float dt  = 60.0f / 69.0f;
    const int tid = threadIdx.x;

    if (tid < NT) {
        float t0 = (float)tid * dt;
        float a = epo_interp(t0);
        float m = epo_interp(t0 + 0.5f * dt);
        sE2[tid].x = pk2(a, a);
        sE2[tid].y = pk2(m, m);
    }
    if (tid < OBS) {
        float d = design[tid];
        float u = d * (69.0f / 60.0f);
        int i = (int)floorf(u);
        if (i < 0) i = 0;
        if (i > NSEG - 1) i = NSEG - 1;
        sIdxS[tid] = i;
        sWS[tid]   = u - (float)i;
    }
    __syncthreads();
    if (tid == 0) {
        int needed[NT];
        #pragma unroll 1
        for (int t = 0; t < NT; ++t) needed[t] = 0;
        int tlast = 1;
        for (int j = 0; j < OBS; ++j) {
            needed[sIdxS[j]]     = 1;
            needed[sIdxS[j] + 1] = 1;
            if (sIdxS[j] + 1 > tlast) tlast = sIdxS[j] + 1;
        }
        int slot = 0;
        #pragma unroll 1
        for (int t = 0; t < NT; ++t)
            sSlot[t] = needed[t] ? slot++ : -1;
        sTLast = tlast;
    }
    __syncthreads();

    int p = blockIdx.x * BLK + tid;      // pair index
    int nPairs = B >> 1;
    if (p >= nPairs) return;
    int b0 = 2 * p, b1 = 2 * p + 1;

    // Coalesced param loads: 6 floats = 3x float2 (24B stride, 8B aligned)
    const float2* pp = (const float2*)(params + (size_t)6 * p);
    float2 q0 = pp[0], q1 = pp[1], q2 = pp[2];

    float k1a  = fmaf(normcdff(q0.x), 2.5f,  0.5f);
    float k2a  = fmaf(normcdff(q0.y), 0.15f, 0.05f);
    float ra   = 8.0f / fmaf(normcdff(q1.x), 6.0f, 4.0f);
    float k1b  = fmaf(normcdff(q1.y), 2.5f,  0.5f);
    float k2b  = fmaf(normcdff(q2.x), 0.15f, 0.05f);
    float rb   = 8.0f / fmaf(normcdff(q2.y), 6.0f, 4.0f);

    const float hdt = 0.5f * dt, dt6 = dt / 6.0f, dt3 = dt / 3.0f;

    // Batch-uniform constants as folded immediates (UR-promotable)
    const ull Hdt  = PKC(0.5f * (60.0f / 69.0f));
    const ull Dt   = PKC(60.0f / 69.0f);
    const ull G    = PKC((60.0f / 69.0f) / 6.0f);
    const ull G2   = PKC((60.0f / 69.0f) / 3.0f);
    const ull C33  = PKC(0.33f);
    const ull C26  = PKC(0.26f);

    // Per-thread packed constants
    const ull K1P  = pk2(k1a, k1b);
    const ull K2P  = pk2(k2a, k2b);
    const ull NK2  = pk2(-k2a, -k2b);

    // k2-folded out-stage functionals (lambda = h*r/2)
    float la = hdt * ra, lb = hdt * rb;
    float la2 = la*la, la3 = la2*la, lb2 = lb*lb, lb3 = lb2*lb;
    const ull P20 = pk2(k2a*(1.0f - la),               k2b*(1.0f - lb));
    const ull P21 = pk2(k2a*la,                        k2b*lb);
    const ull P30 = pk2(k2a*(1.0f - la + la2),         k2b*(1.0f - lb + lb2));
    const ull P31 = pk2(k2a*(la - 2.0f*la2),           k2b*(lb - 2.0f*lb2));
    const ull P32 = pk2(k2a*la2,                       k2b*lb2);
    const ull P40 = pk2(k2a*(1.0f - 2.0f*la + 2.0f*la2 - 2.0f*la3),
                        k2b*(1.0f - 2.0f*lb + 2.0f*lb2 - 2.0f*lb3));
    const ull P41 = pk2(k2a*2.0f*la*(1.0f - 2.0f*la + 3.0f*la2),
                        k2b*2.0f*lb*(1.0f - 2.0f*lb + 3.0f*lb2));
    const ull P42 = pk2(k2a*2.0f*la2*(1.0f - 3.0f*la), k2b*2.0f*lb2*(1.0f - 3.0f*lb));
    const ull P43 = pk2(k2a*2.0f*la3,                  k2b*2.0f*lb3);

    // Chain RK4 propagator coefficients
    float ca[14], cb[14];
    chain_coefs(dt * ra, ca);
    chain_coefs(dt * rb, cb);
    const ull M0  = pk2(ca[0],  cb[0]);
    const ull M1  = pk2(ca[1],  cb[1]);
    const ull M2  = pk2(ca[2],  cb[2]);
    const ull M3  = pk2(ca[3],  cb[3]);
    const ull M4  = pk2(ca[4],  cb[4]);
    const ull V11 = pk2(ca[5],  cb[5]);
    const ull V12 = pk2(ca[6],  cb[6]);
    const ull V13 = pk2(ca[7],  cb[7]);
    const ull V21 = pk2(ca[8],  cb[8]);
    const ull V22 = pk2(ca[9],  cb[9]);
    const ull V31 = pk2(ca[10], cb[10]);
    const ull V41 = pk2(ca[11], cb[11]);
    const ull V32 = pk2(ca[12], cb[12]);
    const ull V23 = pk2(ca[13], cb[13]);

    // State: x[0..2] = x1,x2,x3; x[3..10] = q1..q7,out
    ull x[NS];
    #pragma unroll
    for (int i = 0; i < NS; ++i) x[i] = 0ULL;
    x[0] = pk2(3.71f, 3.71f);

    {
        int sl = sSlot[0];
        if (sl >= 0) {
            const float y2s = 0.26f * 3.71f;
            sY1[sl][tid] = 0ULL;
            sY2[sl][tid] = pk2(y2s, y2s);
        }
    }

    const int tLast = sTLast;   // block-uniform; steps beyond are unobserved

    ulonglong2 eCur = sE2[0];   // (Ea(0), Em(0))

    #pragma unroll 3
    for (int t = 0; t < tLast; ++t) {
        ulonglong2 eNext = sE2[t + 1];      // prefetch; Ec(t) = eNext.x
        ull Ea = eCur.x, Em = eCur.y, Ec = eNext.x;

        // ---- k2-scaled out-stage values (linear functionals of old chain) ----
        ull k2o1 = f2mul(K2P, x[10]);
        ull k2o2 = f2fma(P21, x[9], f2mul(P20, x[10]));
        ull k2o3 = f2fma(P32, x[8], f2fma(P31, x[9], f2mul(P30, x[10])));
        ull k2o4 = f2fma(P43, x[7], f2fma(P42, x[8],
                   f2fma(P41, x[9], f2mul(P40, x[10]))));

        // ---- Nonlinear block (x1,x2,x3), classic 4-stage RK4 ----
        ull kE, t1, xsq, s0, s1, s2;
        ull xn0, xn1, xn2, xt0, xt1, xt2;

        // stage 1
        kE  = f2mul(K1P, Ea);
        t1  = f2mul(kE, x[0]);
        xsq = f2mul(x[1], x[1]);
        s2 = f2fma(NK2, x[2], xsq);
        s1 = f2sub(t1, xsq);
        s0 = f2sub(k2o1, t1);
        xn0 = f2fma(G, s0, x[0]); xt0 = f2fma(Hdt, s0, x[0]);
        xn1 = f2fma(G, s1, x[1]); xt1 = f2fma(Hdt, s1, x[1]);
        xn2 = f2fma(G, s2, x[2]); xt2 = f2fma(Hdt, s2, x[2]);
        ull u1 = x[2];
        ull u2 = xt2;

        // stage 2 (E mid)
        ull kEm = f2mul(K1P, Em);
        t1  = f2mul(kEm, xt0);
        xsq = f2mul(xt1, xt1);
        s2 = f2fma(NK2, xt2, xsq);
        s1 = f2sub(t1, xsq);
        s0 = f2sub(k2o2, t1);
        xn0 = f2fma(G2, s0, xn0); xt0 = f2fma(Hdt, s0, x[0]);
        xn1 = f2fma(G2, s1, xn1); xt1 = f2fma(Hdt, s1, x[1]);
        xn2 = f2fma(G2, s2, xn2); xt2 = f2fma(Hdt, s2, x[2]);
        ull u3 = xt2;

        // stage 3 (E mid)
        t1  = f2mul(kEm, xt0);
        xsq = f2mul(xt1, xt1);
        s2 = f2fma(NK2, xt2, xsq);
        s1 = f2sub(t1, xsq);
        s0 = f2sub(k2o3, t1);
        xn0 = f2fma(G2, s0, xn0); xt0 = f2fma(Dt, s0, x[0]);
        xn1 = f2fma(G2, s1, xn1); xt1 = f2fma(Dt, s1, x[1]);
        xn2 = f2fma(G2, s2, xn2); xt2 = f2fma(Dt, s2, x[2]);
        ull u4 = xt2;

        // stage 4 (E hi)
        ull kEc = f2mul(K1P, Ec);
        t1  = f2mul(kEc, xt0);
        xsq = f2mul(xt1, xt1);
        s2 = f2fma(NK2, xt2, xsq);
        s1 = f2sub(t1, xsq);
        s0 = f2sub(k2o4, t1);
        x[0] = f2fma(G, s0, xn0);
        x[1] = f2fma(G, s1, xn1);
        x[2] = f2fma(G, s2, xn2);

        // ---- Chain update: q' = M q + v-weighted stage inputs ----
        ull a;
        a = f2mul(M0, x[10]); a = f2fma(M1, x[9], a); a = f2fma(M2, x[8], a);
        a = f2fma(M3, x[7], a); x[10] = f2fma(M4, x[6], a);
        a = f2mul(M0, x[9]);  a = f2fma(M1, x[8], a); a = f2fma(M2, x[7], a);
        a = f2fma(M3, x[6], a); x[9] = f2fma(M4, x[5], a);
        a = f2mul(M0, x[8]);  a = f2fma(M1, x[7], a); a = f2fma(M2, x[6], a);
        a = f2fma(M3, x[5], a); x[8] = f2fma(M4, x[4], a);
        a = f2mul(M0, x[7]);  a = f2fma(M1, x[6], a); a = f2fma(M2, x[5], a);
        a = f2fma(M3, x[4], a); x[7] = f2fma(M4, x[3], a);
        a = f2mul(M0, x[6]);  a = f2fma(M1, x[5], a); a = f2fma(M2, x[4], a);
        a = f2fma(M3, x[3], a); x[6] = f2fma(M4, u1, a);
        a = f2mul(M0, x[5]);  a = f2fma(M1, x[4], a); a = f2fma(M2, x[3], a);
        a = f2fma(V13, u1, a); x[5] = f2fma(V23, u2, a);
        a = f2mul(M0, x[4]);  a = f2fma(M1, x[3], a); a = f2fma(V12, u1, a);
        a = f2fma(V22, u2, a); x[4] = f2fma(V32, u3, a);
        a = f2mul(M0, x[3]);  a = f2fma(V11, u1, a); a = f2fma(V21, u2, a);
        a = f2fma(V31, u3, a); x[3] = f2fma(V41, u4, a);

        eCur = eNext;

        // ---- Snapshot observables at flagged steps (uniform branch) ----
        int sl = sSlot[t + 1];
        if (sl >= 0) {
            ull y1 = f2mul(C33, f2add(x[1], x[2]));
            ull y2 = f2mul(C26, f2add(f2add(x[0], x[1]), x[2]));
            sY1[sl][tid] = y1;
            sY2[sl][tid] = y2;
        }
    }

    // ===== Epilogue: design-point interpolation from shared snapshots
    float r0[16], r1[16];
    #pragma unroll
    for (int j = 0; j < OBS; ++j) {
        int   i  = sIdxS[j];
        float w  = sWS[j];
        int   sa = sSlot[i];
        int   sb = sSlot[i + 1];
        ull W  = pk2(w, w);
        ull WM = pk2(1.0f - w, 1.0f - w);

        ull o1v = f2fma(WM, sY1[sa][tid], f2mul(W, sY1[sb][tid]));
        ull o2v = f2fma(WM, sY2[sa][tid], f2mul(W, sY2[sb][tid]));

        float a1, bv1, a2, bv2;
        upk2(o1v, a1, bv1);
        upk2(o2v, a2, bv2);
        r0[j] = a1;  r0[j + 8] = a2;
        r1[j] = bv1; r1[j + 8] = bv2;
    }

    float4*       tr0 = (float4*)(out + (size_t)b0 * 16);
    float4*       tr1 = (float4*)(out + (size_t)b1 * 16);
    float4*       nz0 = (float4*)(out + (size_t)B * 16 + (size_t)b0 * 16);
    float4*       nz1 = (float4*)(out + (size_t)B * 16 + (size_t)b1 * 16);
    const float4* ns0 = (const float4*)(noise + (size_t)b0 * 16);
    const float4* ns1 = (const float4*)(noise + (size_t)b1 * 16);

    #pragma unroll
    for (int q = 0; q < 4; ++q) {
        float4 n0 = ns0[q], n1 = ns1[q];
        tr0[q] = make_float4(r0[4*q], r0[4*q+1], r0[4*q+2], r0[4*q+3]);
        tr1[q] = make_float4(r1[4*q], r1[4*q+1], r1[4*q+2], r1[4*q+3]);
        nz0[q] = make_float4(fmaf(0.01f, n0.x, r0[4*q]),   fmaf(0.01f, n0.y, r0[4*q+1]),
                             fmaf(0.01f, n0.z, r0[4*q+2]), fmaf(0.01f, n0.w, r0[4*q+3]));
        nz1[q] = make_float4(fmaf(0.01f, n1.x, r1[4*q]),   fmaf(0.01f, n1.y, r1[4*q+1]),
                             fmaf(0.01f, n1.z, r1[4*q+2]), fmaf(0.01f, n1.w, r1[4*q+3]));
    }
}

extern "C" void kernel_launch(void* const* d_in, const int* in_sizes, int n_in,
                              void* d_out, int out_size) {
    const float* params = (const float*)d_in[0];
    const float* design = (const float*)d_in[1];
    const float* noise  = (const float*)d_in[2];
    float* out = (float*)d_out;
    int B = in_sizes[0] / 3;

    int nPairs = B >> 1;
    int blocks = (nPairs + BLK - 1) / BLK;
    stats5_kernel<<<blocks, BLK>>>(params, design, noise, out, B);
}

// round 15
// speedup vs baseline: 1.1377x; 1.0515x over previous
#include <cuda_runtime.h>
#include <math.h>

typedef unsigned long long ull;

#define NT    70
#define NSEG  69
#define NS    11
#define OBS   8
#define BLK   128
#define MAXSLOT 16

// Broadcast a (compile-time) float into both halves of a packed f32x2 word.
// Constant-folds to a 64-bit immediate -> uniform -> UR-promotable by ptxas.
#define PKC(f) ((((ull)__float_as_uint(f)) << 32) | (ull)__float_as_uint(f))

__constant__ float c_times[16] = {0.f,2.f,4.f,6.f,8.f,10.f,12.f,14.f,
                                  16.f,18.f,20.f,25.f,30.f,40.f,50.f,60.f};
__constant__ float c_epo[16]   = {0.01713f,0.145f,0.2442f,0.7659f,1.0f,0.8605f,
                                  0.7829f,0.5705f,0.6217f,0.331f,0.3388f,0.3116f,
                                  0.05062f,0.02504f,0.01163f,0.01163f};

// ---- packed f32x2 helpers ----
__device__ __forceinline__ ull pk2(float lo, float hi) {
    ull r; asm("mov.b64 %0, {%1, %2};" : "=l"(r) : "f"(lo), "f"(hi)); return r;
}
__device__ __forceinline__ void upk2(ull v, float& lo, float& hi) {
    asm("mov.b64 {%0, %1}, %2;" : "=f"(lo), "=f"(hi) : "l"(v));
}
__device__ __forceinline__ ull f2fma(ull a, ull b, ull c) {
    ull r; asm("fma.rn.f32x2 %0, %1, %2, %3;" : "=l"(r) : "l"(a), "l"(b), "l"(c)); return r;
}
__device__ __forceinline__ ull f2mul(ull a, ull b) {
    ull r; asm("mul.rn.f32x2 %0, %1, %2;" : "=l"(r) : "l"(a), "l"(b)); return r;
}
__device__ __forceinline__ ull f2add(ull a, ull b) {
    ull r; asm("add.rn.f32x2 %0, %1, %2;" : "=l"(r) : "l"(a), "l"(b)); return r;
}
__device__ __forceinline__ ull f2sub(ull a, ull b) {
    ull r; asm("sub.rn.f32x2 %0, %1, %2;" : "=l"(r) : "l"(a), "l"(b)); return r;
}

__device__ __forceinline__ float epo_interp(float t) {
    if (t <= c_times[0]) return c_epo[0];
    #pragma unroll
    for (int k = 1; k < 16; ++k) {
        if (t <= c_times[k]) {
            float w = (t - c_times[k-1]) / (c_times[k] - c_times[k-1]);
            return c_epo[k-1] + w * (c_epo[k] - c_epo[k-1]);
        }
    }
    return c_epo[15];
}

// RK4 one-step propagator coefficients for the linear delay chain dq/dt = r(prev - q).
__device__ __forceinline__ void chain_coefs(float z, float* c) {
    float z2 = z * z, z3 = z2 * z, z4 = z2 * z2;
    c[0]  = 1.0f - z + 0.5f*z2 - (1.0f/6.0f)*z3 + (1.0f/24.0f)*z4;  // m0
    c[1]  = z - z2 + 0.5f*z3 - (1.0f/6.0f)*z4;                      // m1
    c[2]  = 0.5f*z2 - 0.5f*z3 + 0.25f*z4;                           // m2
    c[3]  = (1.0f/6.0f)*z3 - (1.0f/6.0f)*z4;                        // m3
    c[4]  = (1.0f/24.0f)*z4;                                        // m4 (== v14)
    c[5]  = (1.0f/6.0f)*(z - z2 + 0.5f*z3 - 0.25f*z4);              // v11
    c[6]  = (1.0f/6.0f)*(z2 - z3 + 0.75f*z4);                       // v12
    c[7]  = (1.0f/6.0f)*(0.5f*z3 - 0.75f*z4);                       // v13
    c[8]  = (1.0f/6.0f)*(2.0f*z - z2 + 0.5f*z3);                    // v21
    c[9]  = (1.0f/6.0f)*(z2 - z3);                                  // v22
    c[10] = (1.0f/6.0f)*(2.0f*z - z2);                              // v31
    c[11] = z / 6.0f;                                               // v41
    c[12] = z2 / 6.0f;                                              // v32
    c[13] = z3 / 12.0f;                                             // v23
}

__global__ __launch_bounds__(BLK, 2) void stats5_kernel(
    const float* __restrict__ params,   // (B,3)
    const float* __restrict__ design,   // (8,)
    const float* __restrict__ noise,    // (B,16)
    float* __restrict__ out,            // true (B,16) then noised (B,16)
    int B)
{
    __shared__ ulonglong2 sE2[NT];       // [t] = (Ea(t), Em(t)); Ec(t) = Ea(t+1)
    __shared__ int   sSlot[NT + 1];      // +1 pad so the t+2 prefetch stays in bounds
    __shared__ int   sTLast;
    __shared__ int   sIdxS[OBS];
    __shared__ float sWS[OBS];
    __shared__ ull   sY1[MAXSLOT][BLK];
    __shared__ ull   sY2[MAXSLOT][BLK];

    const float dt  = 60.0f / 69.0f;
    const int tid = threadIdx.x;

    if (tid < NT) {
        float t0 = (float)tid * dt;
        float a = epo_interp(t0);
        float m = epo_interp(t0 + 0.5f * dt);
        sE2[tid].x = pk2(a, a);
        sE2[tid].y = pk2(m, m);
    }
    if (tid < OBS) {
        float d = design[tid];
        float u = d * (69.0f / 60.0f);
        int i = (int)floorf(u);
        if (i < 0) i = 0;
        if (i > NSEG - 1) i = NSEG - 1;
        sIdxS[tid] = i;
        sWS[tid]   = u - (float)i;
    }
    __syncthreads();
    if (tid == 0) {
        int needed[NT];
        #pragma unroll 1
        for (int t = 0; t < NT; ++t) needed[t] = 0;
        int tlast = 1;
        for (int j = 0; j < OBS; ++j) {
            needed[sIdxS[j]]     = 1;
            needed[sIdxS[j] + 1] = 1;
            if (sIdxS[j] + 1 > tlast) tlast = sIdxS[j] + 1;
        }
        int slot = 0;
        #pragma unroll 1
        for (int t = 0; t < NT; ++t)
            sSlot[t] = needed[t] ? slot++ : -1;
        sSlot[NT] = -1;                  // pad for lookahead
        sTLast = tlast;
    }
    __syncthreads();

    int p = blockIdx.x * BLK + tid;      // pair index
    int nPairs = B >> 1;
    if (p >= nPairs) return;
    int b0 = 2 * p, b1 = 2 * p + 1;

    // Coalesced param loads: 6 floats = 3x float2 (24B stride, 8B aligned)
    const float2* pp = (const float2*)(params + (size_t)6 * p);
    float2 q0 = pp[0], q1 = pp[1], q2 = pp[2];

    float k1a  = fmaf(normcdff(q0.x), 2.5f,  0.5f);
    float k2a  = fmaf(normcdff(q0.y), 0.15f, 0.05f);
    float ra   = 8.0f / fmaf(normcdff(q1.x), 6.0f, 4.0f);
    float k1b  = fmaf(normcdff(q1.y), 2.5f,  0.5f);
    float k2b  = fmaf(normcdff(q2.x), 0.15f, 0.05f);
    float rb   = 8.0f / fmaf(normcdff(q2.y), 6.0f, 4.0f);

    const float hdt = 0.5f * dt, dt6 = dt / 6.0f, dt3 = dt / 3.0f;

    // Batch-uniform constants as folded immediates (UR-promotable)
    const ull Hdt  = PKC(0.5f * (60.0f / 69.0f));
    const ull Dt   = PKC(60.0f / 69.0f);
    const ull G    = PKC((60.0f / 69.0f) / 6.0f);
    const ull G2   = PKC((60.0f / 69.0f) / 3.0f);
    const ull C33  = PKC(0.33f);
    const ull C26  = PKC(0.26f);

    // Per-thread packed constants
    const ull K1P  = pk2(k1a, k1b);
    const ull K2P  = pk2(k2a, k2b);
    const ull NK2  = pk2(-k2a, -k2b);

    // k2-folded out-stage functionals (lambda = h*r/2)
    float la = hdt * ra, lb = hdt * rb;
    float la2 = la*la, la3 = la2*la, lb2 = lb*lb, lb3 = lb2*lb;
    const ull P20 = pk2(k2a*(1.0f - la),               k2b*(1.0f - lb));
    const ull P21 = pk2(k2a*la,                        k2b*lb);
    const ull P30 = pk2(k2a*(1.0f - la + la2),         k2b*(1.0f - lb + lb2));
    const ull P31 = pk2(k2a*(la - 2.0f*la2),           k2b*(lb - 2.0f*lb2));
    const ull P32 = pk2(k2a*la2,                       k2b*lb2);
    const ull P40 = pk2(k2a*(1.0f - 2.0f*la + 2.0f*la2 - 2.0f*la3),
                        k2b*(1.0f - 2.0f*lb + 2.0f*lb2 - 2.0f*lb3));
    const ull P41 = pk2(k2a*2.0f*la*(1.0f - 2.0f*la + 3.0f*la2),
                        k2b*2.0f*lb*(1.0f - 2.0f*lb + 3.0f*lb2));
    const ull P42 = pk2(k2a*2.0f*la2*(1.0f - 3.0f*la), k2b*2.0f*lb2*(1.0f - 3.0f*lb));
    const ull P43 = pk2(k2a*2.0f*la3,                  k2b*2.0f*lb3);

    // Chain RK4 propagator coefficients
    float ca[14], cb[14];
    chain_coefs(dt * ra, ca);
    chain_coefs(dt * rb, cb);
    const ull M0  = pk2(ca[0],  cb[0]);
    const ull M1  = pk2(ca[1],  cb[1]);
    const ull M2  = pk2(ca[2],  cb[2]);
    const ull M3  = pk2(ca[3],  cb[3]);
    const ull M4  = pk2(ca[4],  cb[4]);
    const ull V11 = pk2(ca[5],  cb[5]);
    const ull V12 = pk2(ca[6],  cb[6]);
    const ull V13 = pk2(ca[7],  cb[7]);
    const ull V21 = pk2(ca[8],  cb[8]);
    const ull V22 = pk2(ca[9],  cb[9]);
    const ull V31 = pk2(ca[10], cb[10]);
    const ull V41 = pk2(ca[11], cb[11]);
    const ull V32 = pk2(ca[12], cb[12]);
    const ull V23 = pk2(ca[13], cb[13]);

    // State: x[0..2] = x1,x2,x3; x[3..10] = q1..q7,out
    ull x[NS];
    #pragma unroll
    for (int i = 0; i < NS; ++i) x[i] = 0ULL;
    x[0] = pk2(3.71f, 3.71f);

    {
        int sl = sSlot[0];
        if (sl >= 0) {
            const float y2s = 0.26f * 3.71f;
            sY1[sl][tid] = 0ULL;
            sY2[sl][tid] = pk2(y2s, y2s);
        }
    }

    const int tLast = sTLast;   // block-uniform; steps beyond are unobserved

    ulonglong2 eCur = sE2[0];   // (Ea(0), Em(0))
    int slCur = sSlot[1];       // slot id for time t+1 of first iteration

    #pragma unroll 3
    for (int t = 0; t < tLast; ++t) {
        ulonglong2 eNext = sE2[t + 1];      // prefetch; Ec(t) = eNext.x
        int slNext = sSlot[t + 2];          // prefetch slot for next iteration
        ull Ea = eCur.x, Em = eCur.y, Ec = eNext.x;

        // ---- k2-scaled out-stage values (linear functionals of old chain) ----
        ull k2o1 = f2mul(K2P, x[10]);
        ull k2o2 = f2fma(P21, x[9], f2mul(P20, x[10]));
        ull k2o3 = f2fma(P32, x[8], f2fma(P31, x[9], f2mul(P30, x[10])));
        ull k2o4 = f2fma(P43, x[7], f2fma(P42, x[8],
                   f2fma(P41, x[9], f2mul(P40, x[10]))));

        // ---- Nonlinear block (x1,x2,x3), classic 4-stage RK4 ----
        ull kE, t1, xsq, s0, s1, s2;
        ull xn0, xn1, xn2, xt0, xt1, xt2;

        // stage 1
        kE  = f2mul(K1P, Ea);
        t1  = f2mul(kE, x[0]);
        xsq = f2mul(x[1], x[1]);
        s2 = f2fma(NK2, x[2], xsq);
        s1 = f2sub(t1, xsq);
        s0 = f2sub(k2o1, t1);
        xn0 = f2fma(G, s0, x[0]); xt0 = f2fma(Hdt, s0, x[0]);
        xn1 = f2fma(G, s1, x[1]); xt1 = f2fma(Hdt, s1, x[1]);
        xn2 = f2fma(G, s2, x[2]); xt2 = f2fma(Hdt, s2, x[2]);
        ull u1 = x[2];
        ull u2 = xt2;

        // stage 2 (E mid)
        ull kEm = f2mul(K1P, Em);
        t1  = f2mul(kEm, xt0);
        xsq = f2mul(xt1, xt1);
        s2 = f2fma(NK2, xt2, xsq);
        s1 = f2sub(t1, xsq);
        s0 = f2sub(k2o2, t1);
        xn0 = f2fma(G2, s0, xn0); xt0 = f2fma(Hdt, s0, x[0]);
        xn1 = f2fma(G2, s1, xn1); xt1 = f2fma(Hdt, s1, x[1]);
        xn2 = f2fma(G2, s2, xn2); xt2 = f2fma(Hdt, s2, x[2]);
        ull u3 = xt2;

        // stage 3 (E mid)
        t1  = f2mul(kEm, xt0);
        xsq = f2mul(xt1, xt1);
        s2 = f2fma(NK2, xt2, xsq);
        s1 = f2sub(t1, xsq);
        s0 = f2sub(k2o3, t1);
        xn0 = f2fma(G2, s0, xn0); xt0 = f2fma(Dt, s0, x[0]);
        xn1 = f2fma(G2, s1, xn1); xt1 = f2fma(Dt, s1, x[1]);
        xn2 = f2fma(G2, s2, xn2); xt2 = f2fma(Dt, s2, x[2]);
        ull u4 = xt2;

        // stage 4 (E hi)
        ull kEc = f2mul(K1P, Ec);
        t1  = f2mul(kEc, xt0);
        xsq = f2mul(xt1, xt1);
        s2 = f2fma(NK2, xt2, xsq);
        s1 = f2sub(t1, xsq);
        s0 = f2sub(k2o4, t1);
        x[0] = f2fma(G, s0, xn0);
        x[1] = f2fma(G, s1, xn1);
        x[2] = f2fma(G, s2, xn2);

        // ---- Chain update: q' = M q + v-weighted stage inputs ----
        ull a;
        a = f2mul(M0, x[10]); a = f2fma(M1, x[9], a); a = f2fma(M2, x[8], a);
        a = f2fma(M3, x[7], a); x[10] = f2fma(M4, x[6], a);
        a = f2mul(M0, x[9]);  a = f2fma(M1, x[8], a); a = f2fma(M2, x[7], a);
        a = f2fma(M3, x[6], a); x[9] = f2fma(M4, x[5], a);
        a = f2mul(M0, x[8]);  a = f2fma(M1, x[7], a); a = f2fma(M2, x[6], a);
        a = f2fma(M3, x[5], a); x[8] = f2fma(M4, x[4], a);
        a = f2mul(M0, x[7]);  a = f2fma(M1, x[6], a); a = f2fma(M2, x[5], a);
        a = f2fma(M3, x[4], a); x[7] = f2fma(M4, x[3], a);
        a = f2mul(M0, x[6]);  a = f2fma(M1, x[5], a); a = f2fma(M2, x[4], a);
        a = f2fma(M3, x[3], a); x[6] = f2fma(M4, u1, a);
        a = f2mul(M0, x[5]);  a = f2fma(M1, x[4], a); a = f2fma(M2, x[3], a);
        a = f2fma(V13, u1, a); x[5] = f2fma(V23, u2, a);
        a = f2mul(M0, x[4]);  a = f2fma(M1, x[3], a); a = f2fma(V12, u1, a);
        a = f2fma(V22, u2, a); x[4] = f2fma(V32, u3, a);
        a = f2mul(M0, x[3]);  a = f2fma(V11, u1, a); a = f2fma(V21, u2, a);
        a = f2fma(V31, u3, a); x[3] = f2fma(V41, u4, a);

        eCur = eNext;

        // ---- Snapshot observables at flagged steps (uniform branch) ----
        if (slCur >= 0) {
            ull y1 = f2mul(C33, f2add(x[1], x[2]));
            ull y2 = f2mul(C26, f2add(f2add(x[0], x[1]), x[2]));
            sY1[slCur][tid] = y1;
            sY2[slCur][tid] = y2;
        }
        slCur = slNext;
    }

    // ===== Epilogue: design-point interpolation from shared snapshots
    float r0[16], r1[16];
    #pragma unroll
    for (int j = 0; j < OBS; ++j) {
        int   i  = sIdxS[j];
        float w  = sWS[j];
        int   sa = sSlot[i];
        int   sb = sSlot[i + 1];
        ull W  = pk2(w, w);
        ull WM = pk2(1.0f - w, 1.0f - w);

        ull o1v = f2fma(WM, sY1[sa][tid], f2mul(W, sY1[sb][tid]));
        ull o2v = f2fma(WM, sY2[sa][tid], f2mul(W, sY2[sb][tid]));

        float a1, bv1, a2, bv2;
        upk2(o1v, a1, bv1);
        upk2(o2v, a2, bv2);
        r0[j] = a1;  r0[j + 8] = a2;
        r1[j] = bv1; r1[j + 8] = bv2;
    }

    float4*       tr0 = (float4*)(out + (size_t)b0 * 16);
    float4*       tr1 = (float4*)(out + (size_t)b1 * 16);
    float4*       nz0 = (float4*)(out + (size_t)B * 16 + (size_t)b0 * 16);
    float4*       nz1 = (float4*)(out + (size_t)B * 16 + (size_t)b1 * 16);
    const float4* ns0 = (const float4*)(noise + (size_t)b0 * 16);
    const float4* ns1 = (const float4*)(noise + (size_t)b1 * 16);

    #pragma unroll
    for (int q = 0; q < 4; ++q) {
        float4 n0 = ns0[q], n1 = ns1[q];
        tr0[q] = make_float4(r0[4*q], r0[4*q+1], r0[4*q+2], r0[4*q+3]);
        tr1[q] = make_float4(r1[4*q], r1[4*q+1], r1[4*q+2], r1[4*q+3]);
        nz0[q] = make_float4(fmaf(0.01f, n0.x, r0[4*q]),   fmaf(0.01f, n0.y, r0[4*q+1]),
                             fmaf(0.01f, n0.z, r0[4*q+2]), fmaf(0.01f, n0.w, r0[4*q+3]));
        nz1[q] = make_float4(fmaf(0.01f, n1.x, r1[4*q]),   fmaf(0.01f, n1.y, r1[4*q+1]),
                             fmaf(0.01f, n1.z, r1[4*q+2]), fmaf(0.01f, n1.w, r1[4*q+3]));
    }
}

extern "C" void kernel_launch(void* const* d_in, const int* in_sizes, int n_in,
                              void* d_out, int out_size) {
    const float* params = (const float*)d_in[0];
    const float* design = (const float*)d_in[1];
    const float* noise  = (const float*)d_in[2];
    float* out = (float*)d_out;
    int B = in_sizes[0] / 3;

    int nPairs = B >> 1;
    int blocks = (nPairs + BLK - 1) / BLK;
    stats5_kernel<<<blocks, BLK>>>(params, design, noise, out, B);
}